// round 16
// baseline (speedup 1.0000x reference)
#include <cuda_runtime.h>
#include <cuda_bf16.h>
#include <cuda_fp16.h>
#include <cstdint>
#include <cstddef>

#define NN 100000
#define EE 800000

// ---------------- scratch (static __device__ globals; no allocation) ----------------
__device__ float d_P[NN * 64];
__device__ __half d_Hf[(size_t)EE * 64];
__device__ float d_AGG[NN * 64];
__device__ float d_CB[NN * 96];
__device__ float d_T1[NN * 96];
__device__ float d_T2[NN * 96];
__device__ int   d_dgo[NN];
__device__ int   d_dgi[NN];
__device__ float d_stats[1152];

__device__ __forceinline__ float lrelu(float v) { return v > 0.f ? v : 0.1f * v; }

__device__ __forceinline__ uint32_t pack_hi(float a0, float a1, uint32_t& lo) {
    __nv_bfloat16 h0 = __float2bfloat16(a0), h1 = __float2bfloat16(a1);
    __nv_bfloat16 l0 = __float2bfloat16(a0 - __bfloat162float(h0));
    __nv_bfloat16 l1 = __float2bfloat16(a1 - __bfloat162float(h1));
    lo = (uint32_t)__bfloat16_as_ushort(l0) | ((uint32_t)__bfloat16_as_ushort(l1) << 16);
    return (uint32_t)__bfloat16_as_ushort(h0) | ((uint32_t)__bfloat16_as_ushort(h1) << 16);
}

__device__ __forceinline__ uint32_t pack_hi_f16(float a0, float a1, uint32_t& lo) {
    __half h0 = __float2half(a0), h1 = __float2half(a1);
    __half l0 = __float2half(a0 - __half2float(h0));
    __half l1 = __float2half(a1 - __half2float(h1));
    lo = (uint32_t)__half_as_ushort(l0) | ((uint32_t)__half_as_ushort(l1) << 16);
    return (uint32_t)__half_as_ushort(h0) | ((uint32_t)__half_as_ushort(h1) << 16);
}

template <bool F16>
__device__ __forceinline__ void mma16(float* acc, const uint32_t* a, uint32_t b0, uint32_t b1) {
    if (F16) {
        asm volatile(
            "mma.sync.aligned.m16n8k16.row.col.f32.f16.f16.f32 "
            "{%0,%1,%2,%3}, {%4,%5,%6,%7}, {%8,%9}, {%0,%1,%2,%3};"
            : "+f"(acc[0]), "+f"(acc[1]), "+f"(acc[2]), "+f"(acc[3])
            : "r"(a[0]), "r"(a[1]), "r"(a[2]), "r"(a[3]), "r"(b0), "r"(b1));
    } else {
        asm volatile(
            "mma.sync.aligned.m16n8k16.row.col.f32.bf16.bf16.f32 "
            "{%0,%1,%2,%3}, {%4,%5,%6,%7}, {%8,%9}, {%0,%1,%2,%3};"
            : "+f"(acc[0]), "+f"(acc[1]), "+f"(acc[2]), "+f"(acc[3])
            : "r"(a[0]), "r"(a[1]), "r"(a[2]), "r"(a[3]), "r"(b0), "r"(b1));
    }
}

// ---------------- zero scratch (vectorized) ----------------
__global__ void zero_k(float4* agg4, int* dgo, int* dgi, float* st) {
    int i = blockIdx.x * blockDim.x + threadIdx.x;
    int stride = gridDim.x * blockDim.x;
    for (int j = i; j < NN * 16; j += stride) agg4[j] = make_float4(0.f, 0.f, 0.f, 0.f);
    for (int j = i; j < NN; j += stride) { dgo[j] = 0; dgi[j] = 0; }
    for (int j = i; j < 1152; j += stride) st[j] = 0.f;
}

// ---------------- degree counts ----------------
__global__ void deg_k(const int* __restrict__ ei, int* dgo, int* dgi) {
    int i = blockIdx.x * blockDim.x + threadIdx.x;
    int stride = gridDim.x * blockDim.x;
    for (int e = i; e < EE; e += stride) {
        atomicAdd(&dgo[ei[e]], 1);
        atomicAdd(&dgi[ei[EE + e]], 1);
    }
}

// ---------------- merged 32-wide column stats (3 segments, float4 loads) ----------------
__global__ void __launch_bounds__(256) stats3_k(
        const float4* __restrict__ ea4, const float4* __restrict__ x4,
        const int* __restrict__ dgo, float* __restrict__ cb,
        float* __restrict__ ST) {
    int b = blockIdx.x, tid = threadIdx.x;
    const float4* A; int n4, lb, G, mode;
    float *sum, *sq;
    if (b < 1024)      { mode = 0; A = ea4; n4 = EE * 8; lb = b;        G = 1024; sum = ST + 32;  sq = ST + 128; }
    else if (b < 1280) { mode = 1; A = x4;  n4 = NN * 8; lb = b - 1024; G = 256;  sum = ST;       sq = ST + 96; }
    else               { mode = 2; A = x4;  n4 = NN * 8; lb = b - 1280; G = 256;  sum = ST + 576; sq = ST + 672; }
    int i = lb * 256 + tid, stride = G * 256;
    float s0 = 0.f, s1 = 0.f, s2 = 0.f, s3 = 0.f;
    float q0 = 0.f, q1 = 0.f, q2 = 0.f, q3 = 0.f;
    for (int j = i; j < n4; j += stride) {
        float4 v = A[j];
        if (mode == 2) *(float4*)&cb[(j >> 3) * 96 + (j & 7) * 4] = v;
        float w = 1.f;
        if (mode == 1) w = (float)dgo[j >> 3];
        s0 += w * v.x; q0 += w * v.x * v.x;
        s1 += w * v.y; q1 += w * v.y * v.y;
        s2 += w * v.z; q2 += w * v.z * v.z;
        s3 += w * v.w; q3 += w * v.w * v.w;
    }
    __shared__ float red[1024];
    red[tid * 4 + 0] = s0; red[tid * 4 + 1] = s1;
    red[tid * 4 + 2] = s2; red[tid * 4 + 3] = s3;
    __syncthreads();
    if (tid < 32) {
        int base = tid >> 2, u = tid & 3;
        float a = 0.f;
#pragma unroll
        for (int m = 0; m < 32; m++) a += red[(base + 8 * m) * 4 + u];
        atomicAdd(&sum[tid], a);
    }
    __syncthreads();
    red[tid * 4 + 0] = q0; red[tid * 4 + 1] = q1;
    red[tid * 4 + 2] = q2; red[tid * 4 + 3] = q3;
    __syncthreads();
    if (tid < 32) {
        int base = tid >> 2, u = tid & 3;
        float a = 0.f;
#pragma unroll
        for (int m = 0; m < 32; m++) a += red[(base + 8 * m) * 4 + u];
        atomicAdd(&sq[tid], a);
    }
}

// ---------------- mma.sync fused GEMM with in-kernel BN fold ----------------
// Each block folds BN into W itself: s,t from stats, folded bias (t@Wfull + c),
// and split/transposed W smem image straight from fp32 W (L1-resident).
// default: bf16 3-term split; F16A/CVT16: fp16 2-term. 128 rows/block, 4 warps.
template <int K, int NC, bool RELU, bool STATS, bool GATHERP, bool SCATTER,
          bool DEGBIAS, bool F16A, bool F16OUT, bool CVT16, bool NEEDBIAS>
__global__ void __launch_bounds__(128)
tgemm_k(const float* __restrict__ A, int lda, int M,
        const __half* __restrict__ Af16,
        const float* __restrict__ Wfull, int koff, int kstats,
        const float* __restrict__ gbn, const float* __restrict__ bbn,
        const float* __restrict__ cbn,
        const float* __restrict__ bsum, const float* __restrict__ bsq,
        float inv_cnt,
        float* __restrict__ out, int ldo, int ocol,
        __half* __restrict__ Oh16,
        const float* __restrict__ Pg, const int* __restrict__ gidx,
        const int* __restrict__ degb,
        float* __restrict__ ssum, float* __restrict__ ssq) {
    constexpr bool HALF = F16A || CVT16;
    constexpr int KP = K + 8;
    constexpr int SW = NC + 2;
    constexpr int ABYTES = 128 * KP * 2 * (HALF ? 1 : 2);
    constexpr int STGB = 128 * SW * 4;
    constexpr int S1 = ABYTES > STGB ? ABYTES : STGB;
    constexpr int NT = NC / 8;
    constexpr int KS = K / 16;
    constexpr int TERMS = HALF ? 2 : 3;

    extern __shared__ unsigned char sm[];
    __shared__ float sS[96], tS[96], biasS[96];
    __nv_bfloat16* smAh = (__nv_bfloat16*)sm;
    __nv_bfloat16* smAl = smAh + 128 * KP;       // unused when HALF
    __nv_bfloat16* smWh = (__nv_bfloat16*)(sm + S1);
    __nv_bfloat16* smWl = smWh + NC * KP;
    float* stg = (float*)sm;

    const int tid = threadIdx.x;
    const int lane = tid & 31, wrp = tid >> 5;
    const int g8 = lane >> 2, tg = lane & 3;
    const int row0 = blockIdx.x * 128;

    // ---- BN fold scalars ----
    if (tid < kstats) {
        float m = bsum[tid] * inv_cnt;
        float v = bsq[tid] * inv_cnt - m * m;
        float sc = gbn[tid] * rsqrtf(v + 1e-5f);
        sS[tid] = sc;
        tS[tid] = bbn[tid] - m * sc;
    }
    __syncthreads();

    // ---- folded bias (coalesced over tid) ----
    if (NEEDBIAS && tid < NC) {
        float acc = cbn[tid];
        for (int k = 0; k < kstats; k++) acc += tS[k] * Wfull[k * NC + tid];
        biasS[tid] = acc;
    }

    // ---- W fold + split fill (k-paired -> conflict-free smem stores) ----
    {
        constexpr int KH2 = K / 2;
        for (int i = tid; i < NC * KH2; i += 128) {
            int n = i / KH2, j = i - n * KH2, k = 2 * j;
            float w0 = sS[koff + k]     * Wfull[(koff + k) * NC + n];
            float w1 = sS[koff + k + 1] * Wfull[(koff + k + 1) * NC + n];
            uint32_t hw, lw;
            if (HALF) hw = pack_hi_f16(w0, w1, lw);
            else      hw = pack_hi(w0, w1, lw);
            *(uint32_t*)(smWh + n * KP + k) = hw;
            *(uint32_t*)(smWl + n * KP + k) = lw;
        }
    }
    // ---- A fill ----
    if (F16A) {
        constexpr int K8 = K / 8;
        for (int idx = tid; idx < 128 * K8; idx += 128) {
            int row = idx / K8, k = (idx - row * K8) * 8;
            int g = row0 + row;
            uint4 hw = make_uint4(0u, 0u, 0u, 0u);
            if (g < M) hw = *(const uint4*)(Af16 + (size_t)g * K + k);
            *(uint4*)(smAh + row * KP + k) = hw;
        }
    } else if (CVT16) {
        constexpr int K4 = K / 4;
        for (int idx = tid; idx < 128 * K4; idx += 128) {
            int row = idx / K4, k = (idx - row * K4) * 4;
            int g = row0 + row;
            float4 t = (g < M) ? *(const float4*)(A + (size_t)g * lda + k)
                               : make_float4(0.f, 0.f, 0.f, 0.f);
            __half2 h0 = __floats2half2_rn(t.x, t.y);
            __half2 h1 = __floats2half2_rn(t.z, t.w);
            uint2 w;
            w.x = *(uint32_t*)&h0;
            w.y = *(uint32_t*)&h1;
            *(uint2*)(smAh + row * KP + k) = w;
        }
    } else {
        constexpr int KH = K / 2;
        for (int idx = tid; idx < 128 * KH; idx += 128) {
            int row = idx / KH;
            int k = (idx - row * KH) * 2;
            int g = row0 + row;
            float ax = 0.f, ay = 0.f;
            if (g < M) {
                float2 t = *(const float2*)(A + (size_t)g * lda + k);
                ax = t.x; ay = t.y;
            }
            uint32_t lw, hw = pack_hi(ax, ay, lw);
            *(uint32_t*)(smAh + row * KP + k) = hw;
            *(uint32_t*)(smAl + row * KP + k) = lw;
        }
    }
    __syncthreads();

    // ---- mma compute ----
    float acc[2][NT][4];
#pragma unroll
    for (int mt = 0; mt < 2; mt++)
#pragma unroll
        for (int nt = 0; nt < NT; nt++)
#pragma unroll
            for (int j = 0; j < 4; j++) acc[mt][nt][j] = 0.f;

    const __nv_bfloat16* APTR[3] = {smAh, smAh, smAl};
    const __nv_bfloat16* WPTR[3] = {smWh, smWl, smWh};
#pragma unroll
    for (int t = 0; t < TERMS; t++) {
        const __nv_bfloat16* Ab = APTR[t];
        const __nv_bfloat16* Wb = WPTR[t];
#pragma unroll
        for (int ks = 0; ks < KS; ks++) {
            uint32_t a[2][4];
#pragma unroll
            for (int mt = 0; mt < 2; mt++) {
                int row = wrp * 32 + mt * 16 + g8;
                const uint32_t* p  = (const uint32_t*)(Ab + row * KP + ks * 16 + tg * 2);
                const uint32_t* p8 = (const uint32_t*)(Ab + (row + 8) * KP + ks * 16 + tg * 2);
                a[mt][0] = p[0];  a[mt][1] = p8[0];
                a[mt][2] = p[4];  a[mt][3] = p8[4];
            }
#pragma unroll
            for (int nt = 0; nt < NT; nt++) {
                const uint32_t* q = (const uint32_t*)(Wb + (nt * 8 + g8) * KP + ks * 16 + tg * 2);
                uint32_t b0 = q[0], b1 = q[4];
#pragma unroll
                for (int mt = 0; mt < 2; mt++)
                    mma16<HALF>(acc[mt][nt], a[mt], b0, b1);
            }
        }
    }
    __syncthreads();   // A reads done; staging may overwrite

    // ---- fragments -> staging ----
#pragma unroll
    for (int mt = 0; mt < 2; mt++) {
        int r0 = wrp * 32 + mt * 16 + g8;
#pragma unroll
        for (int nt = 0; nt < NT; nt++) {
            int c = nt * 8 + tg * 2;
            *(float2*)&stg[r0 * SW + c]       = make_float2(acc[mt][nt][0], acc[mt][nt][1]);
            *(float2*)&stg[(r0 + 8) * SW + c] = make_float2(acc[mt][nt][2], acc[mt][nt][3]);
        }
    }
    __syncthreads();

    // ---- warp-cooperative P gather: 16 lanes x float4 per row, 2 rows per pass ----
    if (GATHERP) {
        for (int rr = wrp * 2; rr < 128; rr += 8) {
            int r = rr + (lane >> 4);
            int ch = (lane & 15) * 4;
            int e = row0 + r;
            if (e < M) {
                int src = gidx[e];
                float4 p = *(const float4*)(Pg + (size_t)src * 64 + ch);
                float2 t0 = *(float2*)&stg[r * SW + ch];
                float2 t1 = *(float2*)&stg[r * SW + ch + 2];
                t0.x += p.x; t0.y += p.y; t1.x += p.z; t1.y += p.w;
                *(float2*)&stg[r * SW + ch] = t0;
                *(float2*)&stg[r * SW + ch + 2] = t1;
            }
        }
        __syncthreads();
    }

    // ---- per-row epilogue: thread tid owns row row0+tid; results go back to stg ----
    const int g = row0 + tid;
    const bool valid = g < M;
    int other = 0;
    if (SCATTER && valid) other = gidx[g];
    float db = 1.f;
    if (DEGBIAS) db = valid ? (float)degb[g] : 0.f;

#pragma unroll
    for (int ch = 0; ch < NC; ch += 32) {
        float v[32];
#pragma unroll
        for (int c = 0; c < 32; c += 2) {
            float2 t = *(float2*)&stg[tid * SW + ch + c];
            v[c] = t.x; v[c + 1] = t.y;
        }
#pragma unroll
        for (int j = 0; j < 32; j++) {
            float b = NEEDBIAS ? biasS[ch + j] : 0.f;
            float t = v[j] + db * b;
            if (RELU) t = lrelu(t);
            v[j] = t;
        }
#pragma unroll
        for (int c = 0; c < 32; c += 2)
            *(float2*)&stg[tid * SW + ch + c] =
                make_float2(valid ? v[c] : 0.f, valid ? v[c + 1] : 0.f);
    }
    __syncthreads();

    if (SCATTER) {
        // warp-per-row coalesced scalar atomics (NC == 64) — proven fast path
        for (int r = wrp; r < 128; r += 4) {
            int gr = row0 + r;
            if (gr < M) {
                int dst = gidx[gr];
                float* ap = out + (size_t)dst * 64;
                atomicAdd(ap + lane,      stg[r * SW + lane]);
                atomicAdd(ap + 32 + lane, stg[r * SW + 32 + lane]);
            }
        }
    } else if (F16OUT) {
        // coalesced packed fp16 write (NC == 64): 32 uint32 per row
        for (int i = tid; i < 128 * 32; i += 128) {
            int r = i >> 5, c2 = i & 31;
            int gr = row0 + r;
            if (gr < M) {
                __half h0 = __float2half(stg[r * SW + 2 * c2]);
                __half h1 = __float2half(stg[r * SW + 2 * c2 + 1]);
                uint32_t hw = (uint32_t)__half_as_ushort(h0) |
                              ((uint32_t)__half_as_ushort(h1) << 16);
                ((uint32_t*)Oh16)[(size_t)gr * 32 + c2] = hw;
            }
        }
    } else {
        // coalesced fp32 write: lane-per-column, one contiguous row per warp pass
        constexpr int C2 = NC / 2;
        for (int i = tid; i < 128 * C2; i += 128) {
            int r = i / C2, c2 = i - r * C2;
            int gr = row0 + r;
            if (gr < M)
                *(float2*)(out + (size_t)gr * ldo + ocol + c2 * 2) =
                    *(float2*)&stg[r * SW + c2 * 2];
        }
    }

    if (STATS) {
        if (tid < NC) {
            float s = 0.f, q = 0.f;
            for (int r = 0; r < 128; r++) {
                float t = stg[r * SW + tid];
                s += t; q += t * t;
            }
            atomicAdd(&ssum[tid], s);
            atomicAdd(&ssq[tid], q);
        }
    }
}

// ---------------- host ----------------
#define SYM(ptr, arr) do { void* _p = nullptr; cudaGetSymbolAddress(&_p, arr); ptr = (decltype(ptr))_p; } while (0)

static constexpr int smem_sz(int K, int NC, bool half) {
    int KP = K + 8, SW = NC + 2;
    int abytes = 128 * KP * 2 * (half ? 1 : 2);
    int stgb = 128 * SW * 4;
    int s1 = abytes > stgb ? abytes : stgb;
    return s1 + 2 * NC * KP * 2;
}

extern "C" void kernel_launch(void* const* d_in, const int* in_sizes, int n_in,
                              void* d_out, int out_size) {
    const float* x  = (const float*)d_in[0];
    const int*   ei = (const int*)d_in[1];
    const float* ea = (const float*)d_in[2];
    const float* m1_g1 = (const float*)d_in[5],  *m1_b1 = (const float*)d_in[6];
    const float* m1_w1 = (const float*)d_in[7],  *m1_c1 = (const float*)d_in[8];
    const float* m1_g2 = (const float*)d_in[9],  *m1_b2 = (const float*)d_in[10];
    const float* m1_w2 = (const float*)d_in[11], *m1_c2 = (const float*)d_in[12];
    const float* m1_g3 = (const float*)d_in[13], *m1_b3 = (const float*)d_in[14];
    const float* m1_w3 = (const float*)d_in[15], *m1_c3 = (const float*)d_in[16];
    const float* m2_g1 = (const float*)d_in[17], *m2_b1 = (const float*)d_in[18];
    const float* m2_w1 = (const float*)d_in[19], *m2_c1 = (const float*)d_in[20];
    const float* m2_g2 = (const float*)d_in[21], *m2_b2 = (const float*)d_in[22];
    const float* m2_w2 = (const float*)d_in[23], *m2_c2 = (const float*)d_in[24];
    const float* m2_g3 = (const float*)d_in[25], *m2_b3 = (const float*)d_in[26];
    const float* m2_w3 = (const float*)d_in[27], *m2_c3 = (const float*)d_in[28];

    float *P, *AGG, *CB, *T1, *T2, *ST;
    __half *Hf;
    int *dgo, *dgi;
    SYM(P, d_P); SYM(Hf, d_Hf); SYM(AGG, d_AGG); SYM(CB, d_CB);
    SYM(T1, d_T1); SYM(T2, d_T2); SYM(ST, d_stats);
    SYM(dgo, d_dgo); SYM(dgi, d_dgi);

    float *S0S = ST + 0,   *S0Q = ST + 96;
    float *S2S = ST + 192, *S2Q = ST + 288;
    float *S3S = ST + 384, *S3Q = ST + 480;
    float *B1S = ST + 576, *B1Q = ST + 672;
    float *B2S = ST + 768, *B2Q = ST + 864;
    float *B3S = ST + 960, *B3Q = ST + 1056;

    // <K,NC,RELU,STATS,GATHERP,SCATTER,DEGBIAS,F16A,F16OUT,CVT16,NEEDBIAS>
    auto kP  = tgemm_k<32, 64, false, false, false, false, false, false, false, false, false>;
    auto kE1 = tgemm_k<32, 64, true,  true,  true,  false, false, false, true,  true,  true >;
    auto kE2 = tgemm_k<64, 64, true,  true,  false, true,  false, true,  false, false, true >;
    auto kL3 = tgemm_k<64, 64, false, true,  false, false, true,  false, false, false, true >;
    auto kM2 = tgemm_k<96, 96, true,  true,  false, false, false, false, false, false, true >;
    auto kO  = tgemm_k<96, 32, false, false, false, false, false, false, false, false, true >;

    constexpr int smP  = smem_sz(32, 64, false);
    constexpr int smE1 = smem_sz(32, 64, true);
    constexpr int smE2 = smem_sz(64, 64, true);
    constexpr int smL3 = smem_sz(64, 64, false);
    constexpr int smM2 = smem_sz(96, 96, false);
    constexpr int smO  = smem_sz(96, 32, false);

    cudaFuncSetAttribute(kP,  cudaFuncAttributeMaxDynamicSharedMemorySize, smP);
    cudaFuncSetAttribute(kE1, cudaFuncAttributeMaxDynamicSharedMemorySize, smE1);
    cudaFuncSetAttribute(kE2, cudaFuncAttributeMaxDynamicSharedMemorySize, smE2);
    cudaFuncSetAttribute(kL3, cudaFuncAttributeMaxDynamicSharedMemorySize, smL3);
    cudaFuncSetAttribute(kM2, cudaFuncAttributeMaxDynamicSharedMemorySize, smM2);
    cudaFuncSetAttribute(kO,  cudaFuncAttributeMaxDynamicSharedMemorySize, smO);

    const float invE = 1.f / (float)EE;
    const float invN = 1.f / (float)NN;
    const int EB = EE / 128;             // 6250
    const int NB = (NN + 127) / 128;     // 782

    zero_k<<<2048, 256>>>((float4*)AGG, dgo, dgi, ST);
    deg_k<<<512, 256>>>(ei, dgo, dgi);

    // merged stats (float4): ea stats + degree-weighted x stats + x copy/stats
    stats3_k<<<1536, 256>>>((const float4*)ea, (const float4*)x, dgo, CB, ST);

    // P = x @ fold(BN1, W1)[rows 0:32]   (no bias here; bias applied once in E1)
    kP<<<NB, 128, smP>>>(x, 32, NN, nullptr,
                         m1_w1, 0, 64, m1_g1, m1_b1, nullptr, S0S, S0Q, invE,
                         P, 64, 0, nullptr, nullptr, nullptr, nullptr,
                         nullptr, nullptr);
    // H = lrelu(P[row] + ea(fp16) @ fold(BN1, W1)[rows 32:64] + c1f) -> fp16 Hf; BN2 stats
    kE1<<<EB, 128, smE1>>>(ea, 32, EE, nullptr,
                           m1_w1, 32, 64, m1_g1, m1_b1, m1_c1, S0S, S0Q, invE,
                           nullptr, 0, 0, Hf, P, ei, nullptr,
                           S2S, S2Q);

    // h2 = lrelu(Hf @ fold(BN2, W2) + c2f); BN3 stats; scalar-atomic scatter into AGG
    kE2<<<EB, 128, smE2>>>(nullptr, 0, EE, Hf,
                           m1_w2, 0, 64, m1_g2, m1_b2, m1_c2, S2S, S2Q, invE,
                           AGG, 0, 0, nullptr, nullptr, ei + EE, nullptr,
                           S3S, S3Q);

    // CB[:,32:96] = AGG @ fold(BN3, W3) + deg_in * c3f
    kL3<<<NB, 128, smL3>>>(AGG, 64, NN, nullptr,
                           m1_w3, 0, 64, m1_g3, m1_b3, m1_c3, S3S, S3Q, invE,
                           CB, 96, 32, nullptr, nullptr, nullptr, dgi,
                           B1S + 32, B1Q + 32);

    kM2<<<NB, 128, smM2>>>(CB, 96, NN, nullptr,
                           m2_w1, 0, 96, m2_g1, m2_b1, m2_c1, B1S, B1Q, invN,
                           T1, 96, 0, nullptr, nullptr, nullptr, nullptr,
                           B2S, B2Q);

    kM2<<<NB, 128, smM2>>>(T1, 96, NN, nullptr,
                           m2_w2, 0, 96, m2_g2, m2_b2, m2_c2, B2S, B2Q, invN,
                           T2, 96, 0, nullptr, nullptr, nullptr, nullptr,
                           B3S, B3Q);

    kO<<<NB, 128, smO>>>(T2, 96, NN, nullptr,
                         m2_w3, 0, 96, m2_g3, m2_b3, m2_c3, B3S, B3Q, invN,
                         (float*)d_out, 32, 0, nullptr, nullptr, nullptr, nullptr,
                         nullptr, nullptr);
}

// round 17
// speedup vs baseline: 1.1103x; 1.1103x over previous
#include <cuda_runtime.h>
#include <cuda_bf16.h>
#include <cuda_fp16.h>
#include <cstdint>
#include <cstddef>

#define NN 100000
#define EE 800000

// ---------------- scratch (static __device__ globals; no allocation) ----------------
__device__ __half d_P16[NN * 64];
__device__ __half d_Hf[(size_t)EE * 64];
__device__ float d_AGG[NN * 64];
__device__ float d_CB[NN * 96];
__device__ float d_T1[NN * 96];
__device__ float d_T2[NN * 96];
__device__ int   d_dgo[NN];
__device__ int   d_dgi[NN];
__device__ float d_stats[1152];
__device__ float d_c1f[64], d_c2f[64], d_c3f[64];
__device__ float d_d1f[96], d_d2f[96], d_d3f[32];
// pre-split transposed weight blobs: [Wh: NC*(K+8) x16][Wl: NC*(K+8) x16]
__device__ uint4 d_Bp[640];     // W1 rows 0..31  -> K=32, NC=64, KP=40 (bf16)
__device__ uint4 d_Be1[640];    // W1 rows 32..63 -> K=32, NC=64, KP=40 (fp16)
__device__ uint4 d_Be2[1152];   // W2  K=64, NC=64, KP=72 (fp16)
__device__ uint4 d_Bl3[1152];   // W3  K=64, NC=64, KP=72 (bf16)
__device__ uint4 d_Bm1[2496];   // V1  K=96, NC=96, KP=104 (bf16)
__device__ uint4 d_Bm2[2496];   // V2  K=96, NC=96, KP=104 (bf16)
__device__ uint4 d_Bo[832];     // V3  K=96, NC=32, KP=104 (bf16)

__device__ __forceinline__ float lrelu(float v) { return v > 0.f ? v : 0.1f * v; }

__device__ __forceinline__ uint32_t pack_hi(float a0, float a1, uint32_t& lo) {
    __nv_bfloat16 h0 = __float2bfloat16(a0), h1 = __float2bfloat16(a1);
    __nv_bfloat16 l0 = __float2bfloat16(a0 - __bfloat162float(h0));
    __nv_bfloat16 l1 = __float2bfloat16(a1 - __bfloat162float(h1));
    lo = (uint32_t)__bfloat16_as_ushort(l0) | ((uint32_t)__bfloat16_as_ushort(l1) << 16);
    return (uint32_t)__bfloat16_as_ushort(h0) | ((uint32_t)__bfloat16_as_ushort(h1) << 16);
}

template <bool F16>
__device__ __forceinline__ void mma16(float* acc, const uint32_t* a, uint32_t b0, uint32_t b1) {
    if (F16) {
        asm volatile(
            "mma.sync.aligned.m16n8k16.row.col.f32.f16.f16.f32 "
            "{%0,%1,%2,%3}, {%4,%5,%6,%7}, {%8,%9}, {%0,%1,%2,%3};"
            : "+f"(acc[0]), "+f"(acc[1]), "+f"(acc[2]), "+f"(acc[3])
            : "r"(a[0]), "r"(a[1]), "r"(a[2]), "r"(a[3]), "r"(b0), "r"(b1));
    } else {
        asm volatile(
            "mma.sync.aligned.m16n8k16.row.col.f32.bf16.bf16.f32 "
            "{%0,%1,%2,%3}, {%4,%5,%6,%7}, {%8,%9}, {%0,%1,%2,%3};"
            : "+f"(acc[0]), "+f"(acc[1]), "+f"(acc[2]), "+f"(acc[3])
            : "r"(a[0]), "r"(a[1]), "r"(a[2]), "r"(a[3]), "r"(b0), "r"(b1));
    }
}

// ---------------- zero scratch (vectorized) ----------------
__global__ void zero_k(float4* agg4, int* dgo, int* dgi, float* st) {
    int i = blockIdx.x * blockDim.x + threadIdx.x;
    int stride = gridDim.x * blockDim.x;
    for (int j = i; j < NN * 16; j += stride) agg4[j] = make_float4(0.f, 0.f, 0.f, 0.f);
    for (int j = i; j < NN; j += stride) { dgo[j] = 0; dgi[j] = 0; }
    for (int j = i; j < 1152; j += stride) st[j] = 0.f;
}

// ---------------- degree counts ----------------
__global__ void deg_k(const int* __restrict__ ei, int* dgo, int* dgi) {
    int i = blockIdx.x * blockDim.x + threadIdx.x;
    int stride = gridDim.x * blockDim.x;
    for (int e = i; e < EE; e += stride) {
        atomicAdd(&dgo[ei[e]], 1);
        atomicAdd(&dgi[ei[EE + e]], 1);
    }
}

// ---------------- merged 32-wide column stats (3 segments, float4 loads) ----------------
__global__ void __launch_bounds__(256) stats3_k(
        const float4* __restrict__ ea4, const float4* __restrict__ x4,
        const int* __restrict__ dgo, float* __restrict__ cb,
        float* __restrict__ ST) {
    int b = blockIdx.x, tid = threadIdx.x;
    const float4* A; int n4, lb, G, mode;
    float *sum, *sq;
    if (b < 1024)      { mode = 0; A = ea4; n4 = EE * 8; lb = b;        G = 1024; sum = ST + 32;  sq = ST + 128; }
    else if (b < 1280) { mode = 1; A = x4;  n4 = NN * 8; lb = b - 1024; G = 256;  sum = ST;       sq = ST + 96; }
    else               { mode = 2; A = x4;  n4 = NN * 8; lb = b - 1280; G = 256;  sum = ST + 576; sq = ST + 672; }
    int i = lb * 256 + tid, stride = G * 256;
    float s0 = 0.f, s1 = 0.f, s2 = 0.f, s3 = 0.f;
    float q0 = 0.f, q1 = 0.f, q2 = 0.f, q3 = 0.f;
    for (int j = i; j < n4; j += stride) {
        float4 v = A[j];
        if (mode == 2) *(float4*)&cb[(j >> 3) * 96 + (j & 7) * 4] = v;
        float w = 1.f;
        if (mode == 1) w = (float)dgo[j >> 3];
        s0 += w * v.x; q0 += w * v.x * v.x;
        s1 += w * v.y; q1 += w * v.y * v.y;
        s2 += w * v.z; q2 += w * v.z * v.z;
        s3 += w * v.w; q3 += w * v.w * v.w;
    }
    __shared__ float red[1024];
    red[tid * 4 + 0] = s0; red[tid * 4 + 1] = s1;
    red[tid * 4 + 2] = s2; red[tid * 4 + 3] = s3;
    __syncthreads();
    if (tid < 32) {
        int base = tid >> 2, u = tid & 3;
        float a = 0.f;
#pragma unroll
        for (int m = 0; m < 32; m++) a += red[(base + 8 * m) * 4 + u];
        atomicAdd(&sum[tid], a);
    }
    __syncthreads();
    red[tid * 4 + 0] = q0; red[tid * 4 + 1] = q1;
    red[tid * 4 + 2] = q2; red[tid * 4 + 3] = q3;
    __syncthreads();
    if (tid < 32) {
        int base = tid >> 2, u = tid & 3;
        float a = 0.f;
#pragma unroll
        for (int m = 0; m < 32; m++) a += red[(base + 8 * m) * 4 + u];
        atomicAdd(&sq[tid], a);
    }
}

// ---------------- fold BN into next Linear + emit split/transposed blob ----------------
__global__ void foldprep_k(int K, int NC, int ksplit, int f16a, int f16b,
                           const float* __restrict__ g, const float* __restrict__ b,
                           const float* __restrict__ W, const float* __restrict__ c,
                           const float* __restrict__ ssum, const float* __restrict__ ssq,
                           float inv_cnt,
                           unsigned short* __restrict__ blobA,
                           unsigned short* __restrict__ blobB,
                           float* __restrict__ cf) {
    __shared__ float s[96], t[96];
    int tid = threadIdx.x;
    int gt = blockIdx.x * blockDim.x + tid;
    int GS = gridDim.x * blockDim.x;
    if (tid < K) {
        float m = ssum[tid] * inv_cnt;
        float v = ssq[tid] * inv_cnt - m * m;
        float sc = g[tid] * rsqrtf(v + 1e-5f);
        s[tid] = sc;
        t[tid] = b[tid] - m * sc;
    }
    __syncthreads();
    int KPa = ksplit + 8, KPb = (K - ksplit) + 8;
    for (int j = gt; j < NC; j += GS) {
        float acc = c[j];
        for (int k = 0; k < K; k++) acc += t[k] * W[k * NC + j];
        cf[j] = acc;
    }
    for (int i = gt; i < K * NC; i += GS) {
        int k = i / NC, n = i - k * NC;
        float w = s[k] * W[i];
        int f16 = (k < ksplit) ? f16a : f16b;
        unsigned short hb, lb2;
        if (f16) {
            __half h = __float2half(w);
            __half l = __float2half(w - __half2float(h));
            hb = __half_as_ushort(h); lb2 = __half_as_ushort(l);
        } else {
            __nv_bfloat16 h = __float2bfloat16(w);
            __nv_bfloat16 l = __float2bfloat16(w - __bfloat162float(h));
            hb = __bfloat16_as_ushort(h); lb2 = __bfloat16_as_ushort(l);
        }
        if (k < ksplit) {
            blobA[n * KPa + k] = hb;
            blobA[NC * KPa + n * KPa + k] = lb2;
        } else {
            int kk = k - ksplit;
            blobB[n * KPb + kk] = hb;
            blobB[NC * KPb + n * KPb + kk] = lb2;
        }
    }
}

// ---------------- mma.sync fused GEMM: out[M,NC] = epi(A[M,K] @ W[K,NC]) ----------------
// default: bf16 3-term split; F16A/CVT16: fp16 2-term. 128 rows/block, 4 warps.
// GATHERP: warp-cooperative fp16 P-row gather added into staging before epilogue.
template <int K, int NC, bool RELU, bool STATS, bool GATHERP, bool SCATTER,
          bool DEGBIAS, bool F16A, bool F16OUT, bool CVT16>
__global__ void __launch_bounds__(128)
tgemm_k(const float* __restrict__ A, int lda, int M,
        const __half* __restrict__ Af16,
        const uint4* __restrict__ Bblob,
        const float* __restrict__ bias,
        float* __restrict__ out, int ldo, int ocol,
        __half* __restrict__ Oh16,
        const __half* __restrict__ Pg, const int* __restrict__ gidx,
        const int* __restrict__ degb,
        float* __restrict__ ssum, float* __restrict__ ssq) {
    constexpr bool HALF = F16A || CVT16;
    constexpr int KP = K + 8;
    constexpr int SW = NC + 2;
    constexpr int ABYTES = 128 * KP * 2 * (HALF ? 1 : 2);
    constexpr int STGB = 128 * SW * 4;
    constexpr int S1 = ABYTES > STGB ? ABYTES : STGB;
    constexpr int NT = NC / 8;
    constexpr int KS = K / 16;
    constexpr int TERMS = HALF ? 2 : 3;

    extern __shared__ unsigned char sm[];
    __nv_bfloat16* smAh = (__nv_bfloat16*)sm;
    __nv_bfloat16* smAl = smAh + 128 * KP;       // unused when HALF
    __nv_bfloat16* smWh = (__nv_bfloat16*)(sm + S1);
    __nv_bfloat16* smWl = smWh + NC * KP;
    float* stg = (float*)sm;

    const int tid = threadIdx.x;
    const int lane = tid & 31, wrp = tid >> 5;
    const int g8 = lane >> 2, tg = lane & 3;
    const int row0 = blockIdx.x * 128;

    // ---- W copy (blob layout == smem layout) ----
    {
        uint4* wd = (uint4*)smWh;
        for (int i = tid; i < NC * KP / 4; i += 128) wd[i] = Bblob[i];
    }
    // ---- A fill ----
    if (F16A) {
        constexpr int K8 = K / 8;
        for (int idx = tid; idx < 128 * K8; idx += 128) {
            int row = idx / K8, k = (idx - row * K8) * 8;
            int g = row0 + row;
            uint4 hw = make_uint4(0u, 0u, 0u, 0u);
            if (g < M) hw = *(const uint4*)(Af16 + (size_t)g * K + k);
            *(uint4*)(smAh + row * KP + k) = hw;
        }
    } else if (CVT16) {
        constexpr int K4 = K / 4;
        for (int idx = tid; idx < 128 * K4; idx += 128) {
            int row = idx / K4, k = (idx - row * K4) * 4;
            int g = row0 + row;
            float4 t = (g < M) ? *(const float4*)(A + (size_t)g * lda + k)
                               : make_float4(0.f, 0.f, 0.f, 0.f);
            __half2 h0 = __floats2half2_rn(t.x, t.y);
            __half2 h1 = __floats2half2_rn(t.z, t.w);
            uint2 w;
            w.x = *(uint32_t*)&h0;
            w.y = *(uint32_t*)&h1;
            *(uint2*)(smAh + row * KP + k) = w;
        }
    } else {
        constexpr int KH = K / 2;
        for (int idx = tid; idx < 128 * KH; idx += 128) {
            int row = idx / KH;
            int k = (idx - row * KH) * 2;
            int g = row0 + row;
            float ax = 0.f, ay = 0.f;
            if (g < M) {
                float2 t = *(const float2*)(A + (size_t)g * lda + k);
                ax = t.x; ay = t.y;
            }
            uint32_t lw, hw = pack_hi(ax, ay, lw);
            *(uint32_t*)(smAh + row * KP + k) = hw;
            *(uint32_t*)(smAl + row * KP + k) = lw;
        }
    }
    __syncthreads();

    // ---- mma compute ----
    float acc[2][NT][4];
#pragma unroll
    for (int mt = 0; mt < 2; mt++)
#pragma unroll
        for (int nt = 0; nt < NT; nt++)
#pragma unroll
            for (int j = 0; j < 4; j++) acc[mt][nt][j] = 0.f;

    const __nv_bfloat16* APTR[3] = {smAh, smAh, smAl};
    const __nv_bfloat16* WPTR[3] = {smWh, smWl, smWh};
#pragma unroll
    for (int t = 0; t < TERMS; t++) {
        const __nv_bfloat16* Ab = APTR[t];
        const __nv_bfloat16* Wb = WPTR[t];
#pragma unroll
        for (int ks = 0; ks < KS; ks++) {
            uint32_t a[2][4];
#pragma unroll
            for (int mt = 0; mt < 2; mt++) {
                int row = wrp * 32 + mt * 16 + g8;
                const uint32_t* p  = (const uint32_t*)(Ab + row * KP + ks * 16 + tg * 2);
                const uint32_t* p8 = (const uint32_t*)(Ab + (row + 8) * KP + ks * 16 + tg * 2);
                a[mt][0] = p[0];  a[mt][1] = p8[0];
                a[mt][2] = p[4];  a[mt][3] = p8[4];
            }
#pragma unroll
            for (int nt = 0; nt < NT; nt++) {
                const uint32_t* q = (const uint32_t*)(Wb + (nt * 8 + g8) * KP + ks * 16 + tg * 2);
                uint32_t b0 = q[0], b1 = q[4];
#pragma unroll
                for (int mt = 0; mt < 2; mt++)
                    mma16<HALF>(acc[mt][nt], a[mt], b0, b1);
            }
        }
    }
    __syncthreads();   // A reads done; staging may overwrite

    // ---- fragments -> staging ----
#pragma unroll
    for (int mt = 0; mt < 2; mt++) {
        int r0 = wrp * 32 + mt * 16 + g8;
#pragma unroll
        for (int nt = 0; nt < NT; nt++) {
            int c = nt * 8 + tg * 2;
            *(float2*)&stg[r0 * SW + c]       = make_float2(acc[mt][nt][0], acc[mt][nt][1]);
            *(float2*)&stg[(r0 + 8) * SW + c] = make_float2(acc[mt][nt][2], acc[mt][nt][3]);
        }
    }
    __syncthreads();

    // ---- warp-cooperative fp16 P gather: 16 lanes x uint2 (one 128B line per row) ----
    if (GATHERP) {
        for (int rr = wrp * 2; rr < 128; rr += 8) {
            int r = rr + (lane >> 4);
            int ch = (lane & 15) * 4;
            int e = row0 + r;
            if (e < M) {
                int src = gidx[e];
                const __half2* pr = (const __half2*)(Pg + (size_t)src * 64 + ch);
                float2 f0 = __half22float2(pr[0]);
                float2 f1 = __half22float2(pr[1]);
                float2 t0 = *(float2*)&stg[r * SW + ch];
                float2 t1 = *(float2*)&stg[r * SW + ch + 2];
                t0.x += f0.x; t0.y += f0.y; t1.x += f1.x; t1.y += f1.y;
                *(float2*)&stg[r * SW + ch] = t0;
                *(float2*)&stg[r * SW + ch + 2] = t1;
            }
        }
        __syncthreads();
    }

    // ---- per-row epilogue: thread tid owns row row0+tid; results go back to stg ----
    const int g = row0 + tid;
    const bool valid = g < M;
    int other = 0;
    if (SCATTER && valid) other = gidx[g];
    float db = 1.f;
    if (DEGBIAS) db = valid ? (float)degb[g] : 0.f;

#pragma unroll
    for (int ch = 0; ch < NC; ch += 32) {
        float v[32];
#pragma unroll
        for (int c = 0; c < 32; c += 2) {
            float2 t = *(float2*)&stg[tid * SW + ch + c];
            v[c] = t.x; v[c + 1] = t.y;
        }
#pragma unroll
        for (int j = 0; j < 32; j++) {
            float b = bias ? __ldg(bias + ch + j) : 0.f;
            float t = v[j] + db * b;
            if (RELU) t = lrelu(t);
            v[j] = t;
        }
#pragma unroll
        for (int c = 0; c < 32; c += 2)
            *(float2*)&stg[tid * SW + ch + c] =
                make_float2(valid ? v[c] : 0.f, valid ? v[c + 1] : 0.f);
    }
    __syncthreads();

    if (SCATTER) {
        // warp-per-row coalesced scalar atomics (NC == 64) — proven fast path
        for (int r = wrp; r < 128; r += 4) {
            int gr = row0 + r;
            if (gr < M) {
                int dst = gidx[gr];
                float* ap = out + (size_t)dst * 64;
                atomicAdd(ap + lane,      stg[r * SW + lane]);
                atomicAdd(ap + 32 + lane, stg[r * SW + 32 + lane]);
            }
        }
    } else if (F16OUT) {
        // coalesced packed fp16 write (NC == 64): 32 uint32 per row
        for (int i = tid; i < 128 * 32; i += 128) {
            int r = i >> 5, c2 = i & 31;
            int gr = row0 + r;
            if (gr < M) {
                __half h0 = __float2half(stg[r * SW + 2 * c2]);
                __half h1 = __float2half(stg[r * SW + 2 * c2 + 1]);
                uint32_t hw = (uint32_t)__half_as_ushort(h0) |
                              ((uint32_t)__half_as_ushort(h1) << 16);
                ((uint32_t*)Oh16)[(size_t)gr * 32 + c2] = hw;
            }
        }
    } else {
        // coalesced fp32 write: lane-per-column, one contiguous row per warp pass
        constexpr int C2 = NC / 2;
        for (int i = tid; i < 128 * C2; i += 128) {
            int r = i / C2, c2 = i - r * C2;
            int gr = row0 + r;
            if (gr < M)
                *(float2*)(out + (size_t)gr * ldo + ocol + c2 * 2) =
                    *(float2*)&stg[r * SW + c2 * 2];
        }
    }

    if (STATS) {
        if (tid < NC) {
            float s = 0.f, q = 0.f;
            for (int r = 0; r < 128; r++) {
                float t = stg[r * SW + tid];
                s += t; q += t * t;
            }
            atomicAdd(&ssum[tid], s);
            atomicAdd(&ssq[tid], q);
        }
    }
}

// ---------------- host ----------------
#define SYM(ptr, arr) do { void* _p = nullptr; cudaGetSymbolAddress(&_p, arr); ptr = (decltype(ptr))_p; } while (0)

static constexpr int smem_sz(int K, int NC, bool half) {
    int KP = K + 8, SW = NC + 2;
    int abytes = 128 * KP * 2 * (half ? 1 : 2);
    int stgb = 128 * SW * 4;
    int s1 = abytes > stgb ? abytes : stgb;
    return s1 + 2 * NC * KP * 2;
}

extern "C" void kernel_launch(void* const* d_in, const int* in_sizes, int n_in,
                              void* d_out, int out_size) {
    const float* x  = (const float*)d_in[0];
    const int*   ei = (const int*)d_in[1];
    const float* ea = (const float*)d_in[2];
    const float* m1_g1 = (const float*)d_in[5],  *m1_b1 = (const float*)d_in[6];
    const float* m1_w1 = (const float*)d_in[7],  *m1_c1 = (const float*)d_in[8];
    const float* m1_g2 = (const float*)d_in[9],  *m1_b2 = (const float*)d_in[10];
    const float* m1_w2 = (const float*)d_in[11], *m1_c2 = (const float*)d_in[12];
    const float* m1_g3 = (const float*)d_in[13], *m1_b3 = (const float*)d_in[14];
    const float* m1_w3 = (const float*)d_in[15], *m1_c3 = (const float*)d_in[16];
    const float* m2_g1 = (const float*)d_in[17], *m2_b1 = (const float*)d_in[18];
    const float* m2_w1 = (const float*)d_in[19], *m2_c1 = (const float*)d_in[20];
    const float* m2_g2 = (const float*)d_in[21], *m2_b2 = (const float*)d_in[22];
    const float* m2_w2 = (const float*)d_in[23], *m2_c2 = (const float*)d_in[24];
    const float* m2_g3 = (const float*)d_in[25], *m2_b3 = (const float*)d_in[26];
    const float* m2_w3 = (const float*)d_in[27], *m2_c3 = (const float*)d_in[28];

    float *AGG, *CB, *T1, *T2, *ST;
    __half *Hf, *P16;
    int *dgo, *dgi;
    float *c1f, *c2f, *c3f, *d1f, *d2f, *d3f;
    uint4 *Bp, *Be1, *Be2, *Bl3, *Bm1, *Bm2, *Bo;
    SYM(P16, d_P16); SYM(Hf, d_Hf); SYM(AGG, d_AGG); SYM(CB, d_CB);
    SYM(T1, d_T1); SYM(T2, d_T2); SYM(ST, d_stats);
    SYM(dgo, d_dgo); SYM(dgi, d_dgi);
    SYM(c1f, d_c1f); SYM(c2f, d_c2f); SYM(c3f, d_c3f);
    SYM(d1f, d_d1f); SYM(d2f, d_d2f); SYM(d3f, d_d3f);
    SYM(Bp, d_Bp); SYM(Be1, d_Be1); SYM(Be2, d_Be2); SYM(Bl3, d_Bl3);
    SYM(Bm1, d_Bm1); SYM(Bm2, d_Bm2); SYM(Bo, d_Bo);

    float *S0S = ST + 0,   *S0Q = ST + 96;
    float *S2S = ST + 192, *S2Q = ST + 288;
    float *S3S = ST + 384, *S3Q = ST + 480;
    float *B1S = ST + 576, *B1Q = ST + 672;
    float *B2S = ST + 768, *B2Q = ST + 864;
    float *B3S = ST + 960, *B3Q = ST + 1056;

    // <K,NC,RELU,STATS,GATHERP,SCATTER,DEGBIAS,F16A,F16OUT,CVT16>
    auto kP  = tgemm_k<32, 64, false, false, false, false, false, false, true,  false>;
    auto kE1 = tgemm_k<32, 64, true,  true,  true,  false, false, false, true,  true >;
    auto kE2 = tgemm_k<64, 64, true,  true,  false, true,  false, true,  false, false>;
    auto kL3 = tgemm_k<64, 64, false, true,  false, false, true,  false, false, false>;
    auto kM2 = tgemm_k<96, 96, true,  true,  false, false, false, false, false, false>;
    auto kO  = tgemm_k<96, 32, false, false, false, false, false, false, false, false>;

    constexpr int smP  = smem_sz(32, 64, false);
    constexpr int smE1 = smem_sz(32, 64, true);
    constexpr int smE2 = smem_sz(64, 64, true);
    constexpr int smL3 = smem_sz(64, 64, false);
    constexpr int smM2 = smem_sz(96, 96, false);
    constexpr int smO  = smem_sz(96, 32, false);

    cudaFuncSetAttribute(kP,  cudaFuncAttributeMaxDynamicSharedMemorySize, smP);
    cudaFuncSetAttribute(kE1, cudaFuncAttributeMaxDynamicSharedMemorySize, smE1);
    cudaFuncSetAttribute(kE2, cudaFuncAttributeMaxDynamicSharedMemorySize, smE2);
    cudaFuncSetAttribute(kL3, cudaFuncAttributeMaxDynamicSharedMemorySize, smL3);
    cudaFuncSetAttribute(kM2, cudaFuncAttributeMaxDynamicSharedMemorySize, smM2);
    cudaFuncSetAttribute(kO,  cudaFuncAttributeMaxDynamicSharedMemorySize, smO);

    const float invE = 1.f / (float)EE;
    const float invN = 1.f / (float)NN;
    const int EB = EE / 128;             // 6250
    const int NB = (NN + 127) / 128;     // 782

    zero_k<<<2048, 256>>>((float4*)AGG, dgo, dgi, ST);
    deg_k<<<512, 256>>>(ei, dgo, dgi);

    // merged stats (float4): ea stats + degree-weighted x stats + x copy/stats
    stats3_k<<<1536, 256>>>((const float4*)ea, (const float4*)x, dgo, CB, ST);

    // fold BN1 -> blobs Bp (x-half, bf16) + Be1 (ea-half, fp16), bias c1f
    foldprep_k<<<48, 128>>>(64, 64, 32, 0, 1, m1_g1, m1_b1, m1_w1, m1_c1, S0S, S0Q, invE,
                            (unsigned short*)Bp, (unsigned short*)Be1, c1f);

    // P16 = fp16(x @ W1f[0:32])
    kP<<<NB, 128, smP>>>(x, 32, NN, nullptr, Bp, nullptr,
                         nullptr, 0, 0, P16, nullptr, nullptr, nullptr,
                         nullptr, nullptr);
    // H = lrelu(P16[row] + ea(fp16) @ W1f[32:64] + c1f) -> fp16 Hf; BN2 stats
    kE1<<<EB, 128, smE1>>>(ea, 32, EE, nullptr, Be1, c1f,
                           nullptr, 0, 0, Hf, P16, ei, nullptr, S2S, S2Q);

    // fold BN2 -> Be2 in fp16 2-term
    foldprep_k<<<48, 128>>>(64, 64, 64, 1, 1, m1_g2, m1_b2, m1_w2, m1_c2, S2S, S2Q, invE,
                            (unsigned short*)Be2, nullptr, c2f);

    // h2 = lrelu(Hf @ W2f + c2f); BN3 stats; scalar-atomic scatter into AGG[col]
    kE2<<<EB, 128, smE2>>>(nullptr, 0, EE, Hf, Be2, c2f,
                           AGG, 0, 0, nullptr, nullptr, ei + EE, nullptr,
                           S3S, S3Q);

    foldprep_k<<<48, 128>>>(64, 64, 64, 0, 0, m1_g3, m1_b3, m1_w3, m1_c3, S3S, S3Q, invE,
                            (unsigned short*)Bl3, nullptr, c3f);

    // CB[:,32:96] = AGG @ W3f + deg_in * c3f
    kL3<<<NB, 128, smL3>>>(AGG, 64, NN, nullptr, Bl3, c3f,
                           CB, 96, 32, nullptr, nullptr, nullptr, dgi,
                           B1S + 32, B1Q + 32);

    foldprep_k<<<48, 128>>>(96, 96, 96, 0, 0, m2_g1, m2_b1, m2_w1, m2_c1, B1S, B1Q, invN,
                            (unsigned short*)Bm1, nullptr, d1f);

    kM2<<<NB, 128, smM2>>>(CB, 96, NN, nullptr, Bm1, d1f,
                           T1, 96, 0, nullptr, nullptr, nullptr, nullptr,
                           B2S, B2Q);

    foldprep_k<<<48, 128>>>(96, 96, 96, 0, 0, m2_g2, m2_b2, m2_w2, m2_c2, B2S, B2Q, invN,
                            (unsigned short*)Bm2, nullptr, d2f);

    kM2<<<NB, 128, smM2>>>(T1, 96, NN, nullptr, Bm2, d2f,
                           T2, 96, 0, nullptr, nullptr, nullptr, nullptr,
                           B3S, B3Q);

    foldprep_k<<<48, 128>>>(96, 32, 96, 0, 0, m2_g3, m2_b3, m2_w3, m2_c3, B3S, B3Q, invN,
                            (unsigned short*)Bo, nullptr, d3f);

    kO<<<NB, 128, smO>>>(T2, 96, NN, nullptr, Bo, d3f,
                         (float*)d_out, 32, 0, nullptr, nullptr, nullptr, nullptr,
                         nullptr, nullptr);
}